// round 7
// baseline (speedup 1.0000x reference)
#include <cuda_runtime.h>
#include <cuda_fp16.h>
#include <cuda_bf16.h>
#include <math.h>

// ---------------------------------------------------------------------------
// GATLayers round 7:
//   - gemm2 on tensor cores (mma.sync m16n8k16 fp16 -> fp32), y2/W2 in fp16
//   - hist+gemv1 fused; rowptr+scatter fused (flag-gated, wave-1-safe spin)
//   - everything else = proven round-5/6 paths
// 9 graph nodes: prep | hist+gemv1 | rowptr+scatter | agg1 | gemm1(f32x2,+BN)
//   | gemv2 | agg2 | gemm2(mma,+BN) | bnapply
// ---------------------------------------------------------------------------

constexpr int NN = 20000;
constexpr int EE = 640000;
constexpr int CB = (NN + 255) / 256;   // 79 rowptr blocks
constexpr int HB = EE / 256;           // 2500 hist/scatter blocks
constexpr int GB = (NN + 63) / 64;     // 313 gemm1 row-blocks
constexpr int GB2 = (NN + 127) / 128;  // 157 gemm2 row-blocks

// ------------------------------ scratch ------------------------------------
__device__ int    g_is64;
__device__ int    g_ready;             // rowptr scan flag
__device__ int    g_done;              // rowptr done counter
__device__ int    g_rpdone;            // rowptr->scatter gate
__device__ int    g_tick;              // gemm last-block ticket
__device__ int    g_deg[NN];
__device__ int    g_rowptr[NN + 1];
__device__ int    g_rank[EE];
__device__ int    g_col[EE];
__device__ int    g_bsum[CB];
__device__ __half g_x16[NN * 64];
__device__ __half g_h16[NN * 128];
__device__ __half g_w2t[256 * 128];    // W2^T fp16: [n][k]
__device__ __half g_y2h[NN * 256];     // aggregated layer2, fp16
__device__ float  g_y1[NN * 128];
__device__ float  g_out1[NN * 128];
__device__ float  g_out2[NN * 256];
__device__ float  g_as1[NN * 2];
__device__ float  g_ad1[NN * 2];
__device__ float  g_as2[NN * 2];
__device__ float  g_ad2[NN * 2];
__device__ float  g_part[GB * 2 * 256];
__device__ float  g_scale[256];
__device__ float  g_shift[256];
__device__ float4 g_u1[64];
__device__ float4 g_u2[128];

// --------------------------- f32x2 helpers ----------------------------------
__device__ __forceinline__ unsigned long long pack2(float lo, float hi) {
    unsigned long long r;
    asm("mov.b64 %0, {%1, %2};" : "=l"(r)
        : "r"(__float_as_uint(lo)), "r"(__float_as_uint(hi)));
    return r;
}
__device__ __forceinline__ void unpk2(unsigned long long v, float& x, float& y) {
    unsigned a, b;
    asm("mov.b64 {%0, %1}, %2;" : "=r"(a), "=r"(b) : "l"(v));
    x = __uint_as_float(a); y = __uint_as_float(b);
}
__device__ __forceinline__ void ffma2(unsigned long long& d,
                                      unsigned long long a,
                                      unsigned long long b) {
    asm("fma.rn.f32x2 %0, %1, %2, %0;" : "+l"(d) : "l"(a), "l"(b));
}

// ----------------- prep: deg zero + detect + attvec + W2^T ------------------
__global__ __launch_bounds__(256) void prep_kernel(
    const int* __restrict__ ei32,
    const float* __restrict__ W1, const float* __restrict__ s1,
    const float* __restrict__ d1,
    const float* __restrict__ W2, const float* __restrict__ s2,
    const float* __restrict__ d2)
{
    const int bx = blockIdx.x;
    if (bx < 79) {
        int i = bx * 256 + threadIdx.x;
        if (i < NN) g_deg[i] = 0;
        if (bx == 0 && threadIdx.x < 32) {
            int lane = threadIdx.x;
            int a = ei32[2 * lane + 1];
            int b = ei32[2 * (lane + 32) + 1];
            unsigned m = __ballot_sync(0xffffffffu, (a | b) != 0);
            if (lane == 0) g_is64 = (m == 0) ? 1 : 0;
        }
        return;
    }
    if (bx < 103) {    // attention vectors
        const int lane = threadIdx.x & 31;
        const int f = (bx - 79) * 8 + (threadIdx.x >> 5);   // 0..191
        float4 u = make_float4(0.f, 0.f, 0.f, 0.f);
        if (f < 64) {
            #pragma unroll
            for (int c = lane; c < 64; c += 32) {
                float w0 = W1[f * 128 + c], w1 = W1[f * 128 + 64 + c];
                u.x += w0 * s1[c];      u.y += w1 * s1[64 + c];
                u.z += w0 * d1[c];      u.w += w1 * d1[64 + c];
            }
        } else {
            int f2 = f - 64;
            #pragma unroll
            for (int c = lane; c < 128; c += 32) {
                float w0 = W2[f2 * 256 + c], w1 = W2[f2 * 256 + 128 + c];
                u.x += w0 * s2[c];      u.y += w1 * s2[128 + c];
                u.z += w0 * d2[c];      u.w += w1 * d2[128 + c];
            }
        }
        #pragma unroll
        for (int o = 16; o; o >>= 1) {
            u.x += __shfl_xor_sync(0xffffffffu, u.x, o);
            u.y += __shfl_xor_sync(0xffffffffu, u.y, o);
            u.z += __shfl_xor_sync(0xffffffffu, u.z, o);
            u.w += __shfl_xor_sync(0xffffffffu, u.w, o);
        }
        if (lane == 0) {
            if (f < 64) g_u1[f] = u;
            else        g_u2[f - 64] = u;
        }
        return;
    }
    // W2^T fp16 conversion: blocks 103..134, 32768 elements total
    int t4 = (bx - 103) * 256 + threadIdx.x;       // 0..8191
    int e = t4 * 4;                                 // 0..32764
    int k = e >> 8;                                 // 0..127
    int n0 = e & 255;
    float4 w = *(const float4*)&W2[k * 256 + n0];
    g_w2t[(n0 + 0) * 128 + k] = __float2half_rn(w.x);
    g_w2t[(n0 + 1) * 128 + k] = __float2half_rn(w.y);
    g_w2t[(n0 + 2) * 128 + k] = __float2half_rn(w.z);
    g_w2t[(n0 + 3) * 128 + k] = __float2half_rn(w.w);
}

// -------------------------- CSR construction -------------------------------
__device__ __forceinline__ int edge_val(const void* ei, int idx, int is64) {
    if (is64) return (int)((const long long*)ei)[idx];
    return ((const int*)ei)[idx];
}

// --------------------------- score GEMV body --------------------------------
template <int K, bool BN>
__device__ __forceinline__ void gemv_body(
    int node, const float* __restrict__ A, const float4* __restrict__ U,
    float* __restrict__ as_out, float* __restrict__ ad_out,
    __half* __restrict__ h16, int lane)
{
    float4 acc = make_float4(0.f, 0.f, 0.f, 0.f);
    #pragma unroll
    for (int f = lane; f < K; f += 32) {
        float v = A[(size_t)node * K + f];
        if (BN) { v = v * g_scale[f] + g_shift[f]; v = v > 0.f ? v : 0.f; }
        h16[(size_t)node * K + f] = __float2half_rn(v);
        float4 u = U[f];
        acc.x += v * u.x; acc.y += v * u.y;
        acc.z += v * u.z; acc.w += v * u.w;
    }
    #pragma unroll
    for (int o = 16; o; o >>= 1) {
        acc.x += __shfl_xor_sync(0xffffffffu, acc.x, o);
        acc.y += __shfl_xor_sync(0xffffffffu, acc.y, o);
        acc.z += __shfl_xor_sync(0xffffffffu, acc.z, o);
        acc.w += __shfl_xor_sync(0xffffffffu, acc.w, o);
    }
    if (lane == 0) {
        as_out[node * 2 + 0] = acc.x;
        as_out[node * 2 + 1] = acc.y;
        ad_out[node * 2 + 0] = acc.z;
        ad_out[node * 2 + 1] = acc.w;
    }
}

// ---------------------- fused hist + gemv1 ----------------------------------
__global__ __launch_bounds__(256) void hist_gemv1_kernel(
    const void* __restrict__ ei, const float* __restrict__ x,
    const float4* __restrict__ U,
    float* __restrict__ as_out, float* __restrict__ ad_out,
    __half* __restrict__ x16)
{
    const int bx = blockIdx.x;
    if (bx < HB) {
        int e = bx * 256 + threadIdx.x;
        int dst = edge_val(ei, EE + e, g_is64);
        g_rank[e] = atomicAdd(&g_deg[dst], 1);
        return;
    }
    const int node = (bx - HB) * 8 + (threadIdx.x >> 5);
    gemv_body<64, false>(node, x, U, as_out, ad_out, x16, threadIdx.x & 31);
}

// ---------------------- fused rowptr + scatter -------------------------------
// Blocks [0,CB): block scan + cross-block spin scan (wave-1 resident => safe).
// Blocks [CB,CB+HB): wait for g_rpdone flag, then scatter.
__global__ __launch_bounds__(256) void rowptr_scatter_kernel(
    const void* __restrict__ ei)
{
    const int t = threadIdx.x;
    const int bx = blockIdx.x;
    if (bx >= CB) {
        if (t == 0) { while (atomicAdd(&g_rpdone, 0) == 0) {} }
        __syncthreads();
        int e = (bx - CB) * 256 + t;
        int is64 = g_is64;
        int src = edge_val(ei, e, is64);
        int dst = edge_val(ei, EE + e, is64);
        g_col[g_rowptr[dst] + g_rank[e]] = src;
        return;
    }
    __shared__ int s[256];
    const int i = bx * 256 + t;
    int d = (i < NN) ? g_deg[i] : 0;
    s[t] = d;
    __syncthreads();
    for (int o = 1; o < 256; o <<= 1) {
        int u = (t >= o) ? s[t - o] : 0;
        __syncthreads();
        s[t] += u;
        __syncthreads();
    }
    const int incl = s[t];
    if (t == 255) {
        g_bsum[bx] = incl;
        __threadfence();
        atomicAdd(&g_ready, 1);
        while (atomicAdd(&g_ready, 0) < CB) {}    // blocks 0..78 co-resident
    }
    __syncthreads();
    int pre = 0;
    for (int b = t; b < bx; b += 256) pre += g_bsum[b];
    #pragma unroll
    for (int o = 16; o; o >>= 1) pre += __shfl_xor_sync(0xffffffffu, pre, o);
    __shared__ int ws[8];
    if ((t & 31) == 0) ws[t >> 5] = pre;
    __syncthreads();
    if (t == 0) {
        int p = 0;
        #pragma unroll
        for (int w = 0; w < 8; w++) p += ws[w];
        s[0] = p;
    }
    __syncthreads();
    const int bpre = s[0];
    if (i < NN) g_rowptr[i] = bpre + incl - d;
    if (i == NN - 1) g_rowptr[NN] = bpre + incl;
    __threadfence();
    __syncthreads();
    if (t == 0 && atomicAdd(&g_done, 1) == CB - 1) {
        g_ready = 0;
        g_done = 0;
        __threadfence();
        atomicExch(&g_rpdone, 1);   // release: all rowptr stores visible
    }
}

__global__ __launch_bounds__(256) void gemv2_kernel(
    const float* __restrict__ A, const float4* __restrict__ U,
    float* __restrict__ as_out, float* __restrict__ ad_out,
    __half* __restrict__ h16)
{
    const int node = blockIdx.x * 8 + (threadIdx.x >> 5);
    gemv_body<128, true>(node, A, U, as_out, ad_out, h16, threadIdx.x & 31);
}

// ------------------- segment softmax + weighted aggregate ------------------
// HALF_OUT: store y as fp16 (layer 2); else fp32 (layer 1).
template <int F, bool HALF_OUT>
__global__ __launch_bounds__(256) void agg_kernel(
    const __half* __restrict__ src16, const float* __restrict__ as,
    const float* __restrict__ ad, float* __restrict__ yf,
    __half* __restrict__ yh)
{
    const int lane = threadIdx.x & 31;
    const int warp = threadIdx.x >> 5;
    const int node = blockIdx.x * 8 + warp;
    constexpr int V = F / 32;
    using RowT = typename std::conditional<V == 2, unsigned, uint2>::type;
    const int base = g_rowptr[node];
    const int deg = g_rowptr[node + 1] - base;
    const float2* as2 = (const float2*)as;
    const float2 adi = ((const float2*)ad)[node];

    float acc0[V], acc1[V];
    #pragma unroll
    for (int v = 0; v < V; v++) { acc0[v] = 0.f; acc1[v] = 0.f; }
    float z0, z1;

    auto accum = [&](RowT u, float p0, float p1) {
        if constexpr (V == 2) {
            float2 f = __half22float2(*(__half2*)&u);
            acc0[0] += p0 * f.x; acc0[1] += p0 * f.y;
            acc1[0] += p1 * f.x; acc1[1] += p1 * f.y;
        } else {
            float2 f0 = __half22float2(*(__half2*)&u.x);
            float2 f1 = __half22float2(*(__half2*)&u.y);
            acc0[0] += p0 * f0.x; acc0[1] += p0 * f0.y;
            acc0[2] += p0 * f1.x; acc0[3] += p0 * f1.y;
            acc1[0] += p1 * f0.x; acc1[1] += p1 * f0.y;
            acc1[2] += p1 * f1.x; acc1[3] += p1 * f1.y;
        }
    };

    {   // self loop
        float2 a = as2[node];
        float e0 = a.x + adi.x; e0 = e0 > 0.f ? e0 : 0.2f * e0;
        float e1 = a.y + adi.y; e1 = e1 > 0.f ? e1 : 0.2f * e1;
        float p0 = __expf(e0), p1 = __expf(e1);
        z0 = p0; z1 = p1;
        RowT u = *(const RowT*)(src16 + (size_t)node * F + lane * V);
        accum(u, p0, p1);
    }
    if (deg > 0) {
        int s = g_col[base];
        float2 a_n = as2[s];
        RowT u_n = *(const RowT*)(src16 + (size_t)s * F + lane * V);
        for (int j = 0; j < deg; j++) {
            float2 a = a_n;
            RowT u = u_n;
            if (j + 1 < deg) {
                int s2 = g_col[base + j + 1];
                a_n = as2[s2];
                u_n = *(const RowT*)(src16 + (size_t)s2 * F + lane * V);
            }
            float e0 = a.x + adi.x; e0 = e0 > 0.f ? e0 : 0.2f * e0;
            float e1 = a.y + adi.y; e1 = e1 > 0.f ? e1 : 0.2f * e1;
            float p0 = __expf(e0), p1 = __expf(e1);
            z0 += p0; z1 += p1;
            accum(u, p0, p1);
        }
    }

    const float i0 = 1.f / z0, i1 = 1.f / z1;
    if constexpr (HALF_OUT) {
        // V == 4 only (layer 2)
        __half* yr = yh + (size_t)node * 2 * F;
        __half2 h0 = __floats2half2_rn(acc0[0] * i0, acc0[1] * i0);
        __half2 h1 = __floats2half2_rn(acc0[2] * i0, acc0[3] * i0);
        uint2 st0; st0.x = *(unsigned*)&h0; st0.y = *(unsigned*)&h1;
        *(uint2*)(yr + lane * 4) = st0;
        __half2 h2 = __floats2half2_rn(acc1[0] * i1, acc1[1] * i1);
        __half2 h3 = __floats2half2_rn(acc1[2] * i1, acc1[3] * i1);
        uint2 st1; st1.x = *(unsigned*)&h2; st1.y = *(unsigned*)&h3;
        *(uint2*)(yr + F + lane * 4) = st1;
    } else {
        float* yr = yf + (size_t)node * 2 * F;
        if constexpr (V == 2) {
            *(float2*)(yr + lane * 2) = make_float2(acc0[0] * i0, acc0[1] * i0);
            *(float2*)(yr + F + lane * 2) = make_float2(acc1[0] * i1, acc1[1] * i1);
        } else {
            *(float4*)(yr + lane * 4) = make_float4(
                acc0[0] * i0, acc0[1] * i0, acc0[2] * i0, acc0[3] * i0);
            *(float4*)(yr + F + lane * 4) = make_float4(
                acc1[0] * i1, acc1[1] * i1, acc1[2] * i1, acc1[3] * i1);
        }
    }
}

// -------------------- gemm1: f32x2 + BN stats + finalize --------------------
template <int TN>
__global__ __launch_bounds__(256) void gemm_kernel(
    const float* __restrict__ A, const float* __restrict__ B,
    const float* __restrict__ bias, const float* __restrict__ gamma,
    const float* __restrict__ beta, float* __restrict__ C,
    int M, int K, int ld)
{
    __shared__ float As[64 * 33];
    __shared__ float Bs[32 * TN];
    constexpr int CG = TN / 4;
    constexpr int RT = CG / 4;
    constexpr int TY = 256 / CG;
    const int tid = threadIdx.x;
    const int tx = tid % CG;
    const int ty = tid / CG;
    const int row0 = blockIdx.x * 64;
    const int cb = blockIdx.y * TN;
    unsigned long long acc[RT][2];
    #pragma unroll
    for (int i = 0; i < RT; i++) { acc[i][0] = 0ull; acc[i][1] = 0ull; }

    for (int k0 = 0; k0 < K; k0 += 32) {
        #pragma unroll
        for (int i = 0; i < 8; i++) {
            int idx = tid + i * 256;
            int r = idx >> 5, c = idx & 31;
            int gr = row0 + r;
            As[r * 33 + c] = (gr < M) ? A[(size_t)gr * ld + cb + k0 + c] : 0.f;
        }
        #pragma unroll
        for (int i = 0; i < TN / 8; i++) {
            int idx = tid + i * 256;
            int r = idx / TN, c = idx % TN;
            Bs[idx] = B[(size_t)(k0 + r) * ld + cb + c];
        }
        __syncthreads();
        #pragma unroll
        for (int kk = 0; kk < 32; kk++) {
            ulonglong2 bv = *(const ulonglong2*)&Bs[kk * TN + tx * 4];
            #pragma unroll
            for (int i = 0; i < RT; i++) {
                float a = As[(ty * RT + i) * 33 + kk];
                unsigned long long aa = pack2(a, a);
                ffma2(acc[i][0], aa, bv.x);
                ffma2(acc[i][1], aa, bv.y);
            }
        }
        __syncthreads();
    }
    float4 bv4 = *(const float4*)&bias[cb + tx * 4];
    float ls[4] = {0.f, 0.f, 0.f, 0.f};
    float lq[4] = {0.f, 0.f, 0.f, 0.f};
    #pragma unroll
    for (int i = 0; i < RT; i++) {
        int gr = row0 + ty * RT + i;
        if (gr < M) {
            float c0, c1, c2, c3;
            unpk2(acc[i][0], c0, c1);
            unpk2(acc[i][1], c2, c3);
            c0 += bv4.x; c1 += bv4.y; c2 += bv4.z; c3 += bv4.w;
            *(float4*)&C[(size_t)gr * ld + cb + tx * 4] =
                make_float4(c0, c1, c2, c3);
            ls[0] += c0; ls[1] += c1; ls[2] += c2; ls[3] += c3;
            lq[0] += c0 * c0; lq[1] += c1 * c1;
            lq[2] += c2 * c2; lq[3] += c3 * c3;
        }
    }
    #pragma unroll
    for (int j = 0; j < 4; j++) {
        As[ty * TN + tx * 4 + j] = ls[j];
        Bs[ty * TN + tx * 4 + j] = lq[j];
    }
    __syncthreads();
    if (tid < TN) {
        float s = 0.f, q = 0.f;
        #pragma unroll
        for (int yy = 0; yy < TY; yy++) {
            s += As[yy * TN + tid];
            q += Bs[yy * TN + tid];
        }
        int col = cb + tid;
        g_part[blockIdx.x * 2 * ld + col] = s;
        g_part[blockIdx.x * 2 * ld + ld + col] = q;
    }
    __shared__ int last;
    __threadfence();
    __syncthreads();
    if (tid == 0)
        last = (atomicAdd(&g_tick, 1) == (int)(gridDim.x * gridDim.y) - 1);
    __syncthreads();
    if (!last) return;
    for (int col = tid; col < ld; col += 256) {
        float s = 0.f, q = 0.f;
        for (int b = 0; b < GB; b++) {
            s += g_part[b * 2 * ld + col];
            q += g_part[b * 2 * ld + ld + col];
        }
        const float mu = s * (1.f / NN);
        const float var = q * (1.f / NN) - mu * mu;
        const float sc = gamma[col] * rsqrtf(var + 1e-5f);
        g_scale[col] = sc;
        g_shift[col] = beta[col] - mu * sc;
    }
    if (tid == 0) { g_tick = 0; g_rpdone = 0; }   // reset gates for replay
}

// -------------------- gemm2: tensor-core mma + BN stats ---------------------
// A = y2h [NN,256] fp16, B = g_w2t [256][128] fp16 (n-major), C = out2 fp32.
// Block: 8 warps (4m x 2n), warp tile 32x32, block tile 128x64.
// grid = (157, 4): blockIdx.y -> head(2) x ncol-block(2).
__global__ __launch_bounds__(256) void gemm2_mma_kernel(
    const __half* __restrict__ A, const float* __restrict__ bias,
    const float* __restrict__ gamma, const float* __restrict__ beta,
    float* __restrict__ C)
{
    __shared__ float s_s[64], s_q[64];
    const int tid = threadIdx.x;
    const int warp = tid >> 5, lane = tid & 31;
    const int mw = warp & 3;
    const int nw = warp >> 1 >> 1;                // warp>>2: 0 or 1
    const int head = blockIdx.y >> 1;
    const int nb = blockIdx.y & 1;
    const int row0 = blockIdx.x * 128 + mw * 32;
    const int cbA = head * 128;
    const int cbC = head * 128 + nb * 64;
    const int nbase = cbC + nw * 32;
    const int g = lane >> 2;
    const int tk = (lane & 3) * 2;
    if (tid < 64) { s_s[tid] = 0.f; s_q[tid] = 0.f; }

    float acc[2][4][4];
    #pragma unroll
    for (int mi = 0; mi < 2; mi++)
        #pragma unroll
        for (int ni = 0; ni < 4; ni++)
            #pragma unroll
            for (int j = 0; j < 4; j++) acc[mi][ni][j] = 0.f;

    const bool ok0a = (row0 + 0 * 16 + g) < NN;
    #pragma unroll 1
    for (int k0 = 0; k0 < 128; k0 += 16) {
        unsigned a[2][4];
        #pragma unroll
        for (int mi = 0; mi < 2; mi++) {
            int r0 = row0 + mi * 16 + g;
            int r1 = r0 + 8;
            bool o0 = r0 < NN, o1 = r1 < NN;
            const __half* p0 = A + (size_t)r0 * 256 + cbA + k0 + tk;
            const __half* p1 = A + (size_t)r1 * 256 + cbA + k0 + tk;
            a[mi][0] = o0 ? *(const unsigned*)p0 : 0u;
            a[mi][1] = o1 ? *(const unsigned*)p1 : 0u;
            a[mi][2] = o0 ? *(const unsigned*)(p0 + 8) : 0u;
            a[mi][3] = o1 ? *(const unsigned*)(p1 + 8) : 0u;
        }
        unsigned bf[4][2];
        #pragma unroll
        for (int ni = 0; ni < 4; ni++) {
            const __half* q = &g_w2t[(nbase + ni * 8 + g) * 128 + k0 + tk];
            bf[ni][0] = *(const unsigned*)q;
            bf[ni][1] = *(const unsigned*)(q + 8);
        }
        #pragma unroll
        for (int mi = 0; mi < 2; mi++)
            #pragma unroll
            for (int ni = 0; ni < 4; ni++) {
                asm volatile(
                    "mma.sync.aligned.m16n8k16.row.col.f32.f16.f16.f32 "
                    "{%0,%1,%2,%3}, {%4,%5,%6,%7}, {%8,%9}, {%0,%1,%2,%3};"
                    : "+f"(acc[mi][ni][0]), "+f"(acc[mi][ni][1]),
                      "+f"(acc[mi][ni][2]), "+f"(acc[mi][ni][3])
                    : "r"(a[mi][0]), "r"(a[mi][1]), "r"(a[mi][2]),
                      "r"(a[mi][3]), "r"(bf[ni][0]), "r"(bf[ni][1]));
            }
    }
    (void)ok0a;
    __syncthreads();   // s_s/s_q zeroed and mma done
    // epilogue: bias, store, column partial sums
    #pragma unroll
    for (int ni = 0; ni < 4; ni++) {
        const int col = nbase + ni * 8 + tk;
        float2 bv = *(const float2*)&bias[col];
        float s0 = 0.f, s1 = 0.f, q0 = 0.f, q1 = 0.f;
        #pragma unroll
        for (int mi = 0; mi < 2; mi++) {
            int r0 = row0 + mi * 16 + g;
            int r1 = r0 + 8;
            float c0 = acc[mi][ni][0] + bv.x;
            float c1 = acc[mi][ni][1] + bv.y;
            float c2 = acc[mi][ni][2] + bv.x;
            float c3 = acc[mi][ni][3] + bv.y;
            if (r0 < NN) {
                *(float2*)&C[(size_t)r0 * 256 + col] = make_float2(c0, c1);
                s0 += c0; s1 += c1; q0 += c0 * c0; q1 += c1 * c1;
            }
            if (r1 < NN) {
                *(float2*)&C[(size_t)r1 * 256 + col] = make_float2(c2, c3);
                s0 += c2; s1 += c3; q0 += c2 * c2; q1 += c3 * c3;
            }
        }
        #pragma unroll
        for (int o = 4; o < 32; o <<= 1) {
            s0 += __shfl_xor_sync(0xffffffffu, s0, o);
            s1 += __shfl_xor_sync(0xffffffffu, s1, o);
            q0 += __shfl_xor_sync(0xffffffffu, q0, o);
            q1 += __shfl_xor_sync(0xffffffffu, q1, o);
        }
        if (g == 0) {
            int cl = nw * 32 + ni * 8 + tk;
            atomicAdd(&s_s[cl], s0);     atomicAdd(&s_s[cl + 1], s1);
            atomicAdd(&s_q[cl], q0);     atomicAdd(&s_q[cl + 1], q1);
        }
    }
    __syncthreads();
    if (tid < 64) {
        g_part[blockIdx.x * 512 + cbC + tid] = s_s[tid];
        g_part[blockIdx.x * 512 + 256 + cbC + tid] = s_q[tid];
    }
    __shared__ int last;
    __threadfence();
    __syncthreads();
    if (tid == 0)
        last = (atomicAdd(&g_tick, 1) == (int)(gridDim.x * gridDim.y) - 1);
    __syncthreads();
    if (!last) return;
    {
        int col = tid;   // 256 threads, 256 cols
        float s = 0.f, q = 0.f;
        for (int b = 0; b < GB2; b++) {
            s += g_part[b * 512 + col];
            q += g_part[b * 512 + 256 + col];
        }
        const float mu = s * (1.f / NN);
        const float var = q * (1.f / NN) - mu * mu;
        const float sc = gamma[col] * rsqrtf(var + 1e-5f);
        g_scale[col] = sc;
        g_shift[col] = beta[col] - mu * sc;
    }
    if (tid == 0) g_tick = 0;
}

__global__ void bnapply_kernel(const float* __restrict__ X,
                               float* __restrict__ Y, int mask, int total) {
    int i = blockIdx.x * blockDim.x + threadIdx.x;
    if (i >= total) return;
    int c = i & mask;
    float y = X[i] * g_scale[c] + g_shift[c];
    Y[i] = y > 0.f ? y : 0.f;
}

// ------------------------------- launcher -----------------------------------
extern "C" void kernel_launch(void* const* d_in, const int* in_sizes, int n_in,
                              void* d_out, int out_size) {
    const float* x        = (const float*)d_in[0];
    const void*  ei       = d_in[1];
    const float* W1       = (const float*)d_in[2];
    const float* att_src1 = (const float*)d_in[3];
    const float* att_dst1 = (const float*)d_in[4];
    const float* bias1    = (const float*)d_in[5];
    const float* gamma1   = (const float*)d_in[6];
    const float* beta1    = (const float*)d_in[7];
    const float* W2       = (const float*)d_in[8];
    const float* att_src2 = (const float*)d_in[9];
    const float* att_dst2 = (const float*)d_in[10];
    const float* bias2    = (const float*)d_in[11];
    const float* gamma2   = (const float*)d_in[12];
    const float* beta2    = (const float*)d_in[13];
    float* out = (float*)d_out;

    __half *x16, *h16, *y2h;
    float *y1, *out1, *out2, *as1, *ad1, *as2, *ad2;
    float4 *u1, *u2;
    cudaGetSymbolAddress((void**)&x16,  g_x16);
    cudaGetSymbolAddress((void**)&h16,  g_h16);
    cudaGetSymbolAddress((void**)&y2h,  g_y2h);
    cudaGetSymbolAddress((void**)&y1,   g_y1);
    cudaGetSymbolAddress((void**)&out1, g_out1);
    cudaGetSymbolAddress((void**)&out2, g_out2);
    cudaGetSymbolAddress((void**)&as1,  g_as1);
    cudaGetSymbolAddress((void**)&ad1,  g_ad1);
    cudaGetSymbolAddress((void**)&as2,  g_as2);
    cudaGetSymbolAddress((void**)&ad2,  g_ad2);
    cudaGetSymbolAddress((void**)&u1,   g_u1);
    cudaGetSymbolAddress((void**)&u2,   g_u2);

    prep_kernel<<<135, 256>>>((const int*)ei, W1, att_src1, att_dst1,
                              W2, att_src2, att_dst2);
    hist_gemv1_kernel<<<HB + NN / 8, 256>>>(ei, x, u1, as1, ad1, x16);
    rowptr_scatter_kernel<<<CB + HB, 256>>>(ei);

    agg_kernel<64, false><<<NN / 8, 256>>>(x16, as1, ad1, y1, nullptr);
    gemm_kernel<64><<<dim3(GB, 2), 256>>>(y1, W1, bias1, gamma1, beta1,
                                          out1, NN, 64, 128);
    gemv2_kernel<<<NN / 8, 256>>>(out1, u2, as2, ad2, h16);
    agg_kernel<128, true><<<NN / 8, 256>>>(h16, as2, ad2, nullptr, y2h);
    gemm2_mma_kernel<<<dim3(GB2, 4), 256>>>(y2h, bias2, gamma2, beta2, out2);
    bnapply_kernel<<<(NN * 256 + 255) / 256, 256>>>(out2, out, 255, NN * 256);
}

// round 8
// speedup vs baseline: 1.1616x; 1.1616x over previous
#include <cuda_runtime.h>
#include <cuda_fp16.h>
#include <cuda_bf16.h>
#include <math.h>
#include <type_traits>

// ---------------------------------------------------------------------------
// GATLayers round 8: R6 skeleton + batched-32 agg (distributed score compute).
// 10 graph nodes:
//  prep | hist | rowptr(spin) | scatter+gemv1 | agg1 | gemm1(+BN) | gemv2
//  | agg2 | gemm2(+BN) | bnapply
// GEMMs on the exact f32x2 path (rel_err 3.9e-4 proven).
// ---------------------------------------------------------------------------

constexpr int NN = 20000;
constexpr int EE = 640000;
constexpr int CB = (NN + 255) / 256;   // 79 scan blocks
constexpr int GB = (NN + 63) / 64;     // 313 gemm row-blocks

// ------------------------------ scratch ------------------------------------
__device__ int    g_is64;
__device__ int    g_ready;
__device__ int    g_done;
__device__ int    g_tick;
__device__ int    g_deg[NN];
__device__ int    g_rowptr[NN + 1];
__device__ int    g_rank[EE];
__device__ int    g_col[EE];
__device__ int    g_bsum[CB];
__device__ __half g_x16[NN * 64];
__device__ __half g_h16[NN * 128];
__device__ float  g_y1[NN * 128];
__device__ float  g_y2[NN * 256];
__device__ float  g_out1[NN * 128];
__device__ float  g_out2[NN * 256];
__device__ float  g_as1[NN * 2];
__device__ float  g_ad1[NN * 2];
__device__ float  g_as2[NN * 2];
__device__ float  g_ad2[NN * 2];
__device__ float  g_part[GB * 2 * 256];
__device__ float  g_scale[256];
__device__ float  g_shift[256];
__device__ float4 g_u1[64];
__device__ float4 g_u2[128];

// --------------------------- f32x2 helpers ----------------------------------
__device__ __forceinline__ unsigned long long pack2(float lo, float hi) {
    unsigned long long r;
    asm("mov.b64 %0, {%1, %2};" : "=l"(r)
        : "r"(__float_as_uint(lo)), "r"(__float_as_uint(hi)));
    return r;
}
__device__ __forceinline__ void unpk2(unsigned long long v, float& x, float& y) {
    unsigned a, b;
    asm("mov.b64 {%0, %1}, %2;" : "=r"(a), "=r"(b) : "l"(v));
    x = __uint_as_float(a); y = __uint_as_float(b);
}
__device__ __forceinline__ void ffma2(unsigned long long& d,
                                      unsigned long long a,
                                      unsigned long long b) {
    asm("fma.rn.f32x2 %0, %1, %2, %0;" : "+l"(d) : "l"(a), "l"(b));
}

// ----------------- prep: deg zero + dtype detect + attvec -------------------
__global__ __launch_bounds__(256) void prep_kernel(
    const int* __restrict__ ei32,
    const float* __restrict__ W1, const float* __restrict__ s1,
    const float* __restrict__ d1,
    const float* __restrict__ W2, const float* __restrict__ s2,
    const float* __restrict__ d2)
{
    const int bx = blockIdx.x;
    if (bx < 79) {
        int i = bx * 256 + threadIdx.x;
        if (i < NN) g_deg[i] = 0;
        if (bx == 0 && threadIdx.x < 32) {
            int lane = threadIdx.x;
            int a = ei32[2 * lane + 1];
            int b = ei32[2 * (lane + 32) + 1];
            unsigned m = __ballot_sync(0xffffffffu, (a | b) != 0);
            if (lane == 0) g_is64 = (m == 0) ? 1 : 0;
        }
        return;
    }
    const int lane = threadIdx.x & 31;
    const int f = (bx - 79) * 8 + (threadIdx.x >> 5);   // 0..191
    float4 u = make_float4(0.f, 0.f, 0.f, 0.f);
    if (f < 64) {
        #pragma unroll
        for (int c = lane; c < 64; c += 32) {
            float w0 = W1[f * 128 + c], w1 = W1[f * 128 + 64 + c];
            u.x += w0 * s1[c];      u.y += w1 * s1[64 + c];
            u.z += w0 * d1[c];      u.w += w1 * d1[64 + c];
        }
    } else {
        int f2 = f - 64;
        #pragma unroll
        for (int c = lane; c < 128; c += 32) {
            float w0 = W2[f2 * 256 + c], w1 = W2[f2 * 256 + 128 + c];
            u.x += w0 * s2[c];      u.y += w1 * s2[128 + c];
            u.z += w0 * d2[c];      u.w += w1 * d2[128 + c];
        }
    }
    #pragma unroll
    for (int o = 16; o; o >>= 1) {
        u.x += __shfl_xor_sync(0xffffffffu, u.x, o);
        u.y += __shfl_xor_sync(0xffffffffu, u.y, o);
        u.z += __shfl_xor_sync(0xffffffffu, u.z, o);
        u.w += __shfl_xor_sync(0xffffffffu, u.w, o);
    }
    if (lane == 0) {
        if (f < 64) g_u1[f] = u;
        else        g_u2[f - 64] = u;
    }
}

// -------------------------- CSR construction -------------------------------
__device__ __forceinline__ int edge_val(const void* ei, int idx, int is64) {
    if (is64) return (int)((const long long*)ei)[idx];
    return ((const int*)ei)[idx];
}

__global__ void hist_kernel(const void* __restrict__ ei) {
    int e = blockIdx.x * blockDim.x + threadIdx.x;
    if (e >= EE) return;
    int dst = edge_val(ei, EE + e, g_is64);
    g_rank[e] = atomicAdd(&g_deg[dst], 1);
}

// Fused block-sum + global scan + rowptr: 79 blocks = one wave, spin is safe.
__global__ __launch_bounds__(256) void rowptr_kernel() {
    __shared__ int s[256];
    const int t = threadIdx.x;
    const int bx = blockIdx.x;
    const int i = bx * 256 + t;
    int d = (i < NN) ? g_deg[i] : 0;
    s[t] = d;
    __syncthreads();
    for (int o = 1; o < 256; o <<= 1) {
        int u = (t >= o) ? s[t - o] : 0;
        __syncthreads();
        s[t] += u;
        __syncthreads();
    }
    const int incl = s[t];
    if (t == 255) {
        g_bsum[bx] = incl;
        __threadfence();
        atomicAdd(&g_ready, 1);
        while (atomicAdd(&g_ready, 0) < (int)gridDim.x) {}
    }
    __syncthreads();
    int pre = 0;
    for (int b = t; b < bx; b += 256) pre += g_bsum[b];
    #pragma unroll
    for (int o = 16; o; o >>= 1) pre += __shfl_xor_sync(0xffffffffu, pre, o);
    __shared__ int ws[8];
    if ((t & 31) == 0) ws[t >> 5] = pre;
    __syncthreads();
    if (t == 0) {
        int p = 0;
        #pragma unroll
        for (int w = 0; w < 8; w++) p += ws[w];
        s[0] = p;
    }
    __syncthreads();
    const int bpre = s[0];
    if (i < NN) g_rowptr[i] = bpre + incl - d;
    if (i == NN - 1) g_rowptr[NN] = bpre + incl;
    if (t == 0 && atomicAdd(&g_done, 1) == (int)gridDim.x - 1) {
        g_ready = 0;
        g_done = 0;
    }
}

// ---------------- fused scatter (blocks < SB) + gemv1 (rest) ----------------
constexpr int SB = EE / 256;          // 2500 scatter blocks

template <int K, bool BN>
__device__ __forceinline__ void gemv_body(
    int node, const float* __restrict__ A, const float4* __restrict__ U,
    float* __restrict__ as_out, float* __restrict__ ad_out,
    __half* __restrict__ h16, int lane)
{
    float4 acc = make_float4(0.f, 0.f, 0.f, 0.f);
    #pragma unroll
    for (int f = lane; f < K; f += 32) {
        float v = A[(size_t)node * K + f];
        if (BN) { v = v * g_scale[f] + g_shift[f]; v = v > 0.f ? v : 0.f; }
        h16[(size_t)node * K + f] = __float2half_rn(v);
        float4 u = U[f];
        acc.x += v * u.x; acc.y += v * u.y;
        acc.z += v * u.z; acc.w += v * u.w;
    }
    #pragma unroll
    for (int o = 16; o; o >>= 1) {
        acc.x += __shfl_xor_sync(0xffffffffu, acc.x, o);
        acc.y += __shfl_xor_sync(0xffffffffu, acc.y, o);
        acc.z += __shfl_xor_sync(0xffffffffu, acc.z, o);
        acc.w += __shfl_xor_sync(0xffffffffu, acc.w, o);
    }
    if (lane == 0) {
        as_out[node * 2 + 0] = acc.x;
        as_out[node * 2 + 1] = acc.y;
        ad_out[node * 2 + 0] = acc.z;
        ad_out[node * 2 + 1] = acc.w;
    }
}

__global__ __launch_bounds__(256) void scatter_gemv1_kernel(
    const void* __restrict__ ei, const float* __restrict__ x,
    const float4* __restrict__ U,
    float* __restrict__ as_out, float* __restrict__ ad_out,
    __half* __restrict__ x16)
{
    const int bx = blockIdx.x;
    if (bx < SB) {
        int e = bx * 256 + threadIdx.x;
        int is64 = g_is64;
        int src = edge_val(ei, e, is64);
        int dst = edge_val(ei, EE + e, is64);
        g_col[g_rowptr[dst] + g_rank[e]] = src;
        return;
    }
    const int node = (bx - SB) * 8 + (threadIdx.x >> 5);
    gemv_body<64, false>(node, x, U, as_out, ad_out, x16, threadIdx.x & 31);
}

__global__ __launch_bounds__(256) void gemv2_kernel(
    const float* __restrict__ A, const float4* __restrict__ U,
    float* __restrict__ as_out, float* __restrict__ ad_out,
    __half* __restrict__ h16)
{
    const int node = blockIdx.x * 8 + (threadIdx.x >> 5);
    gemv_body<128, true>(node, A, U, as_out, ad_out, h16, threadIdx.x & 31);
}

// ------------------- segment softmax + weighted aggregate ------------------
// Warp per node, both heads. Batched: each lane scores ONE edge of a 32-edge
// batch (kills 32x redundant exp/score work); accumulation broadcasts
// (src, p0, p1) by shfl. z kept as per-lane partials, reduced once.
template <int F>
__global__ __launch_bounds__(256) void agg_kernel(
    const __half* __restrict__ src16, const float* __restrict__ as,
    const float* __restrict__ ad, float* __restrict__ y)
{
    const int lane = threadIdx.x & 31;
    const int warp = threadIdx.x >> 5;
    const int node = blockIdx.x * 8 + warp;
    constexpr int V = F / 32;
    using RowT = typename std::conditional<V == 2, unsigned, uint2>::type;
    const int base = g_rowptr[node];
    const int deg = g_rowptr[node + 1] - base;
    const float2* as2 = (const float2*)as;
    const float2 adi = ((const float2*)ad)[node];

    float acc0[V], acc1[V];
    #pragma unroll
    for (int v = 0; v < V; v++) { acc0[v] = 0.f; acc1[v] = 0.f; }
    float zp0 = 0.f, zp1 = 0.f;   // per-lane partial z

    auto accum = [&](RowT u, float p0, float p1) {
        if constexpr (V == 2) {
            float2 f = __half22float2(*(__half2*)&u);
            acc0[0] += p0 * f.x; acc0[1] += p0 * f.y;
            acc1[0] += p1 * f.x; acc1[1] += p1 * f.y;
        } else {
            float2 f0 = __half22float2(*(__half2*)&u.x);
            float2 f1 = __half22float2(*(__half2*)&u.y);
            acc0[0] += p0 * f0.x; acc0[1] += p0 * f0.y;
            acc0[2] += p0 * f1.x; acc0[3] += p0 * f1.y;
            acc1[0] += p1 * f0.x; acc1[1] += p1 * f0.y;
            acc1[2] += p1 * f1.x; acc1[3] += p1 * f1.y;
        }
    };

    {   // self loop (same value on all lanes; z counted once via lane 0)
        float2 a = as2[node];
        float e0 = a.x + adi.x; e0 = e0 > 0.f ? e0 : 0.2f * e0;
        float e1 = a.y + adi.y; e1 = e1 > 0.f ? e1 : 0.2f * e1;
        float p0 = __expf(e0), p1 = __expf(e1);
        if (lane == 0) { zp0 += p0; zp1 += p1; }
        RowT u = *(const RowT*)(src16 + (size_t)node * F + lane * V);
        accum(u, p0, p1);
    }

    for (int j0 = 0; j0 < deg; j0 += 32) {
        const int nb = min(32, deg - j0);
        int sl = 0; float p0 = 0.f, p1 = 0.f;
        if (lane < nb) {
            sl = g_col[base + j0 + lane];
            float2 a = as2[sl];
            float e0 = a.x + adi.x; e0 = e0 > 0.f ? e0 : 0.2f * e0;
            float e1 = a.y + adi.y; e1 = e1 > 0.f ? e1 : 0.2f * e1;
            p0 = __expf(e0); p1 = __expf(e1);
        }
        zp0 += p0; zp1 += p1;
        if (nb == 32) {
            #pragma unroll 8
            for (int k = 0; k < 32; k++) {
                int sk = __shfl_sync(0xffffffffu, sl, k);
                float q0 = __shfl_sync(0xffffffffu, p0, k);
                float q1 = __shfl_sync(0xffffffffu, p1, k);
                RowT u = *(const RowT*)(src16 + (size_t)sk * F + lane * V);
                accum(u, q0, q1);
            }
        } else {
            for (int k = 0; k < nb; k++) {
                int sk = __shfl_sync(0xffffffffu, sl, k);
                float q0 = __shfl_sync(0xffffffffu, p0, k);
                float q1 = __shfl_sync(0xffffffffu, p1, k);
                RowT u = *(const RowT*)(src16 + (size_t)sk * F + lane * V);
                accum(u, q0, q1);
            }
        }
    }

    #pragma unroll
    for (int o = 16; o; o >>= 1) {
        zp0 += __shfl_xor_sync(0xffffffffu, zp0, o);
        zp1 += __shfl_xor_sync(0xffffffffu, zp1, o);
    }
    const float i0 = 1.f / zp0, i1 = 1.f / zp1;
    float* yr = y + (size_t)node * 2 * F;
    if constexpr (V == 2) {
        *(float2*)(yr + lane * 2)     = make_float2(acc0[0] * i0, acc0[1] * i0);
        *(float2*)(yr + F + lane * 2) = make_float2(acc1[0] * i1, acc1[1] * i1);
    } else {
        *(float4*)(yr + lane * 4) =
            make_float4(acc0[0] * i0, acc0[1] * i0, acc0[2] * i0, acc0[3] * i0);
        *(float4*)(yr + F + lane * 4) =
            make_float4(acc1[0] * i1, acc1[1] * i1, acc1[2] * i1, acc1[3] * i1);
    }
}

// ---------------------- GEMM + BN stats + last-block finalize ---------------
template <int TN>
__global__ __launch_bounds__(256) void gemm_kernel(
    const float* __restrict__ A, const float* __restrict__ B,
    const float* __restrict__ bias, const float* __restrict__ gamma,
    const float* __restrict__ beta, float* __restrict__ C,
    int M, int K, int ld)
{
    __shared__ float As[64 * 33];
    __shared__ float Bs[32 * TN];
    constexpr int CG = TN / 4;
    constexpr int RT = CG / 4;
    constexpr int TY = 256 / CG;
    const int tid = threadIdx.x;
    const int tx = tid % CG;
    const int ty = tid / CG;
    const int row0 = blockIdx.x * 64;
    const int cb = blockIdx.y * TN;
    unsigned long long acc[RT][2];
    #pragma unroll
    for (int i = 0; i < RT; i++) { acc[i][0] = 0ull; acc[i][1] = 0ull; }

    for (int k0 = 0; k0 < K; k0 += 32) {
        #pragma unroll
        for (int i = 0; i < 8; i++) {
            int idx = tid + i * 256;
            int r = idx >> 5, c = idx & 31;
            int gr = row0 + r;
            As[r * 33 + c] = (gr < M) ? A[(size_t)gr * ld + cb + k0 + c] : 0.f;
        }
        #pragma unroll
        for (int i = 0; i < TN / 8; i++) {
            int idx = tid + i * 256;
            int r = idx / TN, c = idx % TN;
            Bs[idx] = B[(size_t)(k0 + r) * ld + cb + c];
        }
        __syncthreads();
        #pragma unroll
        for (int kk = 0; kk < 32; kk++) {
            ulonglong2 bv = *(const ulonglong2*)&Bs[kk * TN + tx * 4];
            #pragma unroll
            for (int i = 0; i < RT; i++) {
                float a = As[(ty * RT + i) * 33 + kk];
                unsigned long long aa = pack2(a, a);
                ffma2(acc[i][0], aa, bv.x);
                ffma2(acc[i][1], aa, bv.y);
            }
        }
        __syncthreads();
    }
    float4 bv4 = *(const float4*)&bias[cb + tx * 4];
    float ls[4] = {0.f, 0.f, 0.f, 0.f};
    float lq[4] = {0.f, 0.f, 0.f, 0.f};
    #pragma unroll
    for (int i = 0; i < RT; i++) {
        int gr = row0 + ty * RT + i;
        if (gr < M) {
            float c0, c1, c2, c3;
            unpk2(acc[i][0], c0, c1);
            unpk2(acc[i][1], c2, c3);
            c0 += bv4.x; c1 += bv4.y; c2 += bv4.z; c3 += bv4.w;
            *(float4*)&C[(size_t)gr * ld + cb + tx * 4] =
                make_float4(c0, c1, c2, c3);
            ls[0] += c0; ls[1] += c1; ls[2] += c2; ls[3] += c3;
            lq[0] += c0 * c0; lq[1] += c1 * c1;
            lq[2] += c2 * c2; lq[3] += c3 * c3;
        }
    }
    #pragma unroll
    for (int j = 0; j < 4; j++) {
        As[ty * TN + tx * 4 + j] = ls[j];
        Bs[ty * TN + tx * 4 + j] = lq[j];
    }
    __syncthreads();
    if (tid < TN) {
        float s = 0.f, q = 0.f;
        #pragma unroll
        for (int yy = 0; yy < TY; yy++) {
            s += As[yy * TN + tid];
            q += Bs[yy * TN + tid];
        }
        int col = cb + tid;
        g_part[blockIdx.x * 2 * ld + col] = s;
        g_part[blockIdx.x * 2 * ld + ld + col] = q;
    }
    __shared__ int last;
    __threadfence();
    __syncthreads();
    if (tid == 0)
        last = (atomicAdd(&g_tick, 1) == (int)(gridDim.x * gridDim.y) - 1);
    __syncthreads();
    if (!last) return;
    for (int col = tid; col < ld; col += 256) {
        float s = 0.f, q = 0.f;
        for (int b = 0; b < GB; b++) {
            s += g_part[b * 2 * ld + col];
            q += g_part[b * 2 * ld + ld + col];
        }
        const float mu = s * (1.f / NN);
        const float var = q * (1.f / NN) - mu * mu;
        const float sc = gamma[col] * rsqrtf(var + 1e-5f);
        g_scale[col] = sc;
        g_shift[col] = beta[col] - mu * sc;
    }
    if (tid == 0) g_tick = 0;
}

__global__ void bnapply_kernel(const float* __restrict__ X,
                               float* __restrict__ Y, int mask, int total) {
    int i = blockIdx.x * blockDim.x + threadIdx.x;
    if (i >= total) return;
    int c = i & mask;
    float y = X[i] * g_scale[c] + g_shift[c];
    Y[i] = y > 0.f ? y : 0.f;
}

// ------------------------------- launcher -----------------------------------
extern "C" void kernel_launch(void* const* d_in, const int* in_sizes, int n_in,
                              void* d_out, int out_size) {
    const float* x        = (const float*)d_in[0];
    const void*  ei       = d_in[1];
    const float* W1       = (const float*)d_in[2];
    const float* att_src1 = (const float*)d_in[3];
    const float* att_dst1 = (const float*)d_in[4];
    const float* bias1    = (const float*)d_in[5];
    const float* gamma1   = (const float*)d_in[6];
    const float* beta1    = (const float*)d_in[7];
    const float* W2       = (const float*)d_in[8];
    const float* att_src2 = (const float*)d_in[9];
    const float* att_dst2 = (const float*)d_in[10];
    const float* bias2    = (const float*)d_in[11];
    const float* gamma2   = (const float*)d_in[12];
    const float* beta2    = (const float*)d_in[13];
    float* out = (float*)d_out;

    __half *x16, *h16;
    float *y1, *y2, *out1, *out2, *as1, *ad1, *as2, *ad2;
    float4 *u1, *u2;
    cudaGetSymbolAddress((void**)&x16,  g_x16);
    cudaGetSymbolAddress((void**)&h16,  g_h16);
    cudaGetSymbolAddress((void**)&y1,   g_y1);
    cudaGetSymbolAddress((void**)&y2,   g_y2);
    cudaGetSymbolAddress((void**)&out1, g_out1);
    cudaGetSymbolAddress((void**)&out2, g_out2);
    cudaGetSymbolAddress((void**)&as1,  g_as1);
    cudaGetSymbolAddress((void**)&ad1,  g_ad1);
    cudaGetSymbolAddress((void**)&as2,  g_as2);
    cudaGetSymbolAddress((void**)&ad2,  g_ad2);
    cudaGetSymbolAddress((void**)&u1,   g_u1);
    cudaGetSymbolAddress((void**)&u2,   g_u2);

    prep_kernel<<<103, 256>>>((const int*)ei, W1, att_src1, att_dst1,
                              W2, att_src2, att_dst2);
    hist_kernel<<<EE / 256, 256>>>(ei);
    rowptr_kernel<<<CB, 256>>>();
    scatter_gemv1_kernel<<<SB + NN / 8, 256>>>(ei, x, u1, as1, ad1, x16);

    agg_kernel<64><<<NN / 8, 256>>>(x16, as1, ad1, y1);
    gemm_kernel<64><<<dim3(GB, 2), 256>>>(y1, W1, bias1, gamma1, beta1,
                                          out1, NN, 64, 128);
    gemv2_kernel<<<NN / 8, 256>>>(out1, u2, as2, ad2, h16);
    agg_kernel<128><<<NN / 8, 256>>>(h16, as2, ad2, y2);
    gemm_kernel<128><<<dim3(GB, 2), 256>>>(y2, W2, bias2, gamma2, beta2,
                                           out2, NN, 128, 256);
    bnapply_kernel<<<(NN * 256 + 255) / 256, 256>>>(out2, out, 255, NN * 256);
}